// round 17
// baseline (speedup 1.0000x reference)
#include <cuda_runtime.h>
#include <math.h>
#include <stdint.h>

// Problem constants
constexpr int Lc    = 50;
constexpr int NSEQ  = 32 * 40;     // 1280 sequences
constexpr int NR    = NSEQ * Lc;   // 64000 (seq,time) rows
constexpr int H     = 128;
constexpr int G4    = 512;         // 4*H gates

// ---------------------------------------------------------------------------
// Device scratch
// ---------------------------------------------------------------------------
__device__ float g_X0[(size_t)NR * 64];
__device__ float g_Xa[(size_t)NR * 256];
__device__ float g_Xb[(size_t)NR * 256];
__device__ float g_xg[2][(size_t)NR * G4];   // t-major: [dir][t][seq][512]
__device__ float g_agg[(size_t)NSEQ * 768];
__device__ float g_t1[(size_t)NSEQ * 512];
__device__ float g_t2[(size_t)NSEQ * 512];

// ---------------------------------------------------------------------------
// helpers
// ---------------------------------------------------------------------------
__device__ __forceinline__ float2 pack2(float lo, float hi) {
    float2 r; r.x = lo; r.y = hi; return r;
}
__device__ __forceinline__ float sigm_(float x) {
    return __fdividef(1.0f, 1.0f + __expf(-x));
}
__device__ __forceinline__ float tanh_(float x) {
    return __fdividef(2.0f, 1.0f + __expf(-2.0f * x)) - 1.0f;
}
__device__ __forceinline__ uint32_t f2tf(float x) {
    uint32_t r;
    asm("cvt.rna.tf32.f32 %0, %1;" : "=r"(r) : "f"(x));
    return r;
}
__device__ __forceinline__ void mma_tf32(float* d, const uint32_t* a,
                                         const uint32_t* b) {
    asm volatile(
        "mma.sync.aligned.m16n8k8.row.col.f32.tf32.tf32.f32 "
        "{%0,%1,%2,%3}, {%4,%5,%6,%7}, {%8,%9}, {%0,%1,%2,%3};\n"
        : "+f"(d[0]), "+f"(d[1]), "+f"(d[2]), "+f"(d[3])
        : "r"(a[0]), "r"(a[1]), "r"(a[2]), "r"(a[3]), "r"(b[0]), "r"(b[1]));
}
__device__ __forceinline__ uint32_t smem_u32(const void* p) {
    uint32_t a;
    asm("{ .reg .u64 t; cvta.to.shared.u64 t, %1; cvt.u32.u64 %0, t; }"
        : "=r"(a) : "l"(p));
    return a;
}

// ---------------------------------------------------------------------------
// Kernel 1: input projection
// ---------------------------------------------------------------------------
__global__ __launch_bounds__(256) void inproj_kernel(
    const float* __restrict__ imu, const float* __restrict__ Win,
    const float* __restrict__ bin)
{
    int idx = blockIdx.x * 256 + threadIdx.x;
    int row = idx >> 6;
    int jj  = idx & 63;
    int l   = row % Lc;
    const float* xr = imu + (size_t)row * 6;
    float t    = (float)l * (1.0f / 49.0f);
    float rate = 1.0f;
    float acc = bin[jj];
#pragma unroll
    for (int k = 0; k < 6; k++) acc = fmaf(xr[k], Win[k * 64 + jj], acc);
    acc = fmaf(t,    Win[6 * 64 + jj], acc);
    acc = fmaf(rate, Win[7 * 64 + jj], acc);
    g_X0[(size_t)row * 64 + jj] = fmaxf(acc, 0.0f);
}

// ---------------------------------------------------------------------------
// Kernel 2: tf32 tensor-core GEMM + bias (round-13 winner: 2-stage).
// Block tile 128x256, BK=16, 8 warps (2x4) of 64x64 warp tiles, m16n8k8.
// ---------------------------------------------------------------------------
constexpr int APITCH = 132;
constexpr int BPITCH = 516;
constexpr int ASZ = 2 * 8 * APITCH;
constexpr int BSZ = 2 * 4 * BPITCH;
constexpr int GEMM_SMEM = (2 * ASZ + 2 * BSZ) * 4;   // 49,920 bytes

__device__ __forceinline__ int asI(int buf, int ks, int c, int q) {
    return ((buf * 2 + ks) * 8 + c) * APITCH + q;
}
__device__ __forceinline__ int bsI(int buf, int ks, int kp, int q) {
    return ((buf * 2 + ks) * 4 + kp) * BPITCH + q;
}

__global__ __launch_bounds__(256) void tf32_gemm(
    const float* __restrict__ A, const float* __restrict__ B,
    float* __restrict__ C,
    const float* __restrict__ bias1, const float* __restrict__ bias2,
    int M, int N, int K,
    long long sB, long long sC, long long sBias, int nbx, int permute)
{
    extern __shared__ uint32_t sm[];
    uint32_t* As = sm;
    uint32_t* Bs = sm + 2 * ASZ;

    const int dir = blockIdx.x / nbx;
    const int nb  = blockIdx.x % nbx;
    const int mb  = blockIdx.y;
    B += (size_t)dir * sB;
    C += (size_t)dir * sC;
    const float* b1 = bias1 + (size_t)dir * sBias;
    const float* b2 = bias2 ? bias2 + (size_t)dir * sBias : nullptr;
    const bool hasB2 = (b2 != nullptr);

    const int tid  = threadIdx.x;
    const int warp = tid >> 5, lane = tid & 31;
    const int wR = warp >> 2, wC = warp & 3;
    const int g  = lane >> 2, tig = lane & 3;

    const float* Ab = A + (size_t)(mb * 128) * K;
    const float* Bb = B + nb * 256;

    const int aRow = tid >> 1;
    const int aks  = tid & 1;
    const int aQ   = ((aRow >> 4) << 4) + ((aRow & 7) << 1) + ((aRow >> 3) & 1);
    const int bk   = tid >> 4;
    const int bks  = bk >> 3, br8 = bk & 7;
    const int bkp  = br8 & 3, bhalf = br8 >> 2;
    const int bn0  = (tid & 15) * 4;

    float acc[4][8][4];
#pragma unroll
    for (int mt = 0; mt < 4; mt++)
#pragma unroll
        for (int nt = 0; nt < 8; nt++)
#pragma unroll
            for (int q = 0; q < 4; q++) acc[mt][nt][q] = 0.0f;

    const int niter = K / 16;

    {
#pragma unroll
        for (int j = 0; j < 2; j++) {
            float4 v = *(const float4*)(Ab + (size_t)aRow * K + aks * 8 + j * 4);
            uint32_t* d = &As[asI(0, aks, j * 4, aQ)];
            d[0] = f2tf(v.x); d[APITCH] = f2tf(v.y);
            d[2 * APITCH] = f2tf(v.z); d[3 * APITCH] = f2tf(v.w);
        }
#pragma unroll
        for (int i = 0; i < 4; i++) {
            int n0 = bn0 + i * 64;
            float4 v = *(const float4*)(Bb + (size_t)bk * N + n0);
            uint32_t* d = &Bs[bsI(0, bks, bkp, n0 * 2 + bhalf)];
            d[0] = f2tf(v.x); d[2] = f2tf(v.y);
            d[4] = f2tf(v.z); d[6] = f2tf(v.w);
        }
    }
    __syncthreads();

    for (int it = 0; it < niter; it++) {
        const int cur = it & 1, nxt = cur ^ 1;
        const bool more = (it + 1 < niter);
        float4 av[2], bv[4];
        if (more) {
            int k0 = (it + 1) * 16;
#pragma unroll
            for (int j = 0; j < 2; j++)
                av[j] = *(const float4*)(Ab + (size_t)aRow * K + k0 + aks * 8 + j * 4);
#pragma unroll
            for (int i = 0; i < 4; i++)
                bv[i] = *(const float4*)(Bb + (size_t)(k0 + bk) * N + bn0 + i * 64);
        }

#pragma unroll
        for (int ks = 0; ks < 2; ks++) {
            uint32_t af[4][4];
#pragma unroll
            for (int mt = 0; mt < 4; mt++) {
                int q = ((wR * 4 + mt) << 4) + (g << 1);
                uint2 u0 = *(const uint2*)&As[asI(cur, ks, tig, q)];
                uint2 u1 = *(const uint2*)&As[asI(cur, ks, tig + 4, q)];
                af[mt][0] = u0.x; af[mt][1] = u0.y;
                af[mt][2] = u1.x; af[mt][3] = u1.y;
            }
            uint32_t bf[8][2];
#pragma unroll
            for (int nt = 0; nt < 8; nt++) {
                int n = wC * 64 + nt * 8 + g;
                uint2 u = *(const uint2*)&Bs[bsI(cur, ks, tig, n * 2)];
                bf[nt][0] = u.x; bf[nt][1] = u.y;
            }
#pragma unroll
            for (int mt = 0; mt < 4; mt++)
#pragma unroll
                for (int nt = 0; nt < 8; nt++)
                    mma_tf32(acc[mt][nt], af[mt], bf[nt]);
        }

        if (more) {
#pragma unroll
            for (int j = 0; j < 2; j++) {
                uint32_t* d = &As[asI(nxt, aks, j * 4, aQ)];
                d[0] = f2tf(av[j].x); d[APITCH] = f2tf(av[j].y);
                d[2 * APITCH] = f2tf(av[j].z); d[3 * APITCH] = f2tf(av[j].w);
            }
#pragma unroll
            for (int i = 0; i < 4; i++) {
                int n0 = bn0 + i * 64;
                uint32_t* d = &Bs[bsI(nxt, bks, bkp, n0 * 2 + bhalf)];
                d[0] = f2tf(bv[i].x); d[2] = f2tf(bv[i].y);
                d[4] = f2tf(bv[i].z); d[6] = f2tf(bv[i].w);
            }
        }
        __syncthreads();
    }

#pragma unroll
    for (int mt = 0; mt < 4; mt++) {
        int rowa = mb * 128 + wR * 64 + mt * 16 + g;
        int rowb = rowa + 8;
        size_t ra = permute ? ((size_t)(rowa % Lc) * NSEQ + rowa / Lc) : (size_t)rowa;
        size_t rb = permute ? ((size_t)(rowb % Lc) * NSEQ + rowb / Lc) : (size_t)rowb;
#pragma unroll
        for (int nt = 0; nt < 8; nt++) {
            int colg = nb * 256 + wC * 64 + nt * 8 + 2 * tig;
            float bx = b1[colg], by = b1[colg + 1];
            if (hasB2) { bx += b2[colg]; by += b2[colg + 1]; }
            float2 v0 = pack2(acc[mt][nt][0] + bx, acc[mt][nt][1] + by);
            float2 v1 = pack2(acc[mt][nt][2] + bx, acc[mt][nt][3] + by);
            *(float2*)(C + ra * N + colg) = v0;
            *(float2*)(C + rb * N + colg) = v1;
        }
    }
}

// ---------------------------------------------------------------------------
// Kernel 3: PERSISTENT BiLSTM layer — TENSOR-CORE recurrence.
// 128 CTAs (64 clusters of 2) x 512 threads = 16 warps.
// CTA = (dir, jt, rowgroup of 40). Computes D[gc=256][row=40] = Whh^T @ h^T
// via m16n8k8 tf32: warp w owns m-tile gc = w*16 .. w*16+16 where
// gc_local = hc_loc*4 + gate (hidden col = jt*64 + w*4 + hc_loc).
// A (Whh^T, tf32) lives in REGISTERS, loaded once. B (h) split hi+lo tf32
// (two MMAs -> ~fp32 h precision); stored in smem in B-fragment layout,
// double-buffered by step parity; partner half pushed via st.shared::cluster
// + one CTA-wide mbarrier (count 512) per step.
// Gates staged via Dstage[row][gc] smem, then fp32 gate math, c in regs.
// ---------------------------------------------------------------------------
constexpr int NP       = 80;                    // words per (part,kt,kp) row
constexpr int HB_PART  = 16 * 4 * NP;           // words per part
constexpr int HB_BUF   = 2 * HB_PART;           // words per buffer (hi+lo)
constexpr int HB_WORDS = 2 * HB_BUF;            // 40,960 words
constexpr int GP       = 260;                   // Dstage row pitch (words)
constexpr int DS_WORDS = 40 * GP;               // 10,400 words
constexpr int LSTM_SMEM = (HB_WORDS + DS_WORDS) * 4 + 16;   // ~205.5 KB

__global__ __launch_bounds__(512) __cluster_dims__(2, 1, 1)
void lstm_layer(const float* __restrict__ Whh,
                const float* __restrict__ xgb,   // t-major [dir][t][seq][512]
                float* __restrict__ Xout)
{
    extern __shared__ float smem[];
    float* hB  = smem;                 // [2 buf][2 part][16 kt][4 kp][NP]
    float* Dst = smem + HB_WORDS;      // [40][GP]
    unsigned long long* mbar = (unsigned long long*)(Dst + DS_WORDS);

    const int bx   = blockIdx.x;
    const int dir  = bx >> 6;
    const int jt   = bx & 1;                     // cluster rank
    const int rgI  = (bx >> 1) & 31;
    const int row0 = rgI * 40;
    const int tid  = threadIdx.x;
    const int warp = tid >> 5, lane = tid & 31;
    const int g    = lane >> 2, tig = lane & 3;

    const float* W   = Whh + (size_t)dir * (H * G4);
    const float* xgd = xgb + (size_t)dir * NR * G4;

    if (tid == 0) {
        uint32_t mb = smem_u32(mbar);
        asm volatile("mbarrier.init.shared.b64 [%0], %1;"
                     :: "r"(mb), "r"(512) : "memory");
    }

    // A fragments (Whh^T permuted, tf32) -> registers, once.
    // col(gc) = (gc&3)*128 + jt*64 + warp*4 + (gc>>2); col(g+8) = col(g)+2.
    uint32_t a[16][4];
    {
        const int cg0 = (g & 3) * 128 + jt * 64 + warp * 4 + (g >> 2);
#pragma unroll
        for (int kt = 0; kt < 16; kt++) {
            const float* wr0 = W + (size_t)(kt * 8 + tig) * G4;
            const float* wr1 = W + (size_t)(kt * 8 + tig + 4) * G4;
            a[kt][0] = f2tf(wr0[cg0]);
            a[kt][1] = f2tf(wr0[cg0 + 2]);
            a[kt][2] = f2tf(wr1[cg0]);
            a[kt][3] = f2tf(wr1[cg0 + 2]);
        }
    }
    __syncthreads();
    asm volatile("barrier.cluster.arrive.aligned;" ::: "memory");
    asm volatile("barrier.cluster.wait.aligned;" ::: "memory");

    const uint32_t mb_l = smem_u32(mbar);
    uint32_t mb_r;
    asm("mapa.shared::cluster.u32 %0, %1, %2;"
        : "=r"(mb_r) : "r"(mb_l), "r"(jt ^ 1));
    const uint32_t hs_l = smem_u32(hB);
    uint32_t hs_r;
    asm("mapa.shared::cluster.u32 %0, %1, %2;"
        : "=r"(hs_r) : "r"(hs_l), "r"(jt ^ 1));

    // update-phase constants: thread i-th item = (row, hc)
    float c[5];
#pragma unroll
    for (int r = 0; r < 5; r++) c[r] = 0.0f;

    for (int step = 0; step < Lc; step++) {
        const int tin = dir ? (Lc - 1 - step) : step;

        if (step > 0) {
            // wait partner's h(step-1)
            {
                const uint32_t parity = (uint32_t)((step - 1) & 1);
                uint32_t done;
                do {
                    asm volatile(
                        "{\n\t.reg .pred p;\n\t"
                        "mbarrier.try_wait.parity.acquire.cluster.shared::cta.b64 "
                        "p, [%1], %2;\n\t"
                        "selp.b32 %0, 1, 0, p;\n\t}"
                        : "=r"(done) : "r"(mb_l), "r"(parity) : "memory");
                } while (!done);
            }

            // MMA: D = A * (Bhi + Blo) from buffer (step-1)&1
            const float* hbuf = hB + ((step + 1) & 1) * HB_BUF;
#pragma unroll
            for (int nt = 0; nt < 5; nt++) {
                float dd[4] = {0.f, 0.f, 0.f, 0.f};
#pragma unroll
                for (int kt = 0; kt < 16; kt++) {
                    const int boff = (kt * 4 + tig) * NP + (nt * 8 + g) * 2;
                    uint2 uhi = *(const uint2*)(hbuf + boff);
                    uint2 ulo = *(const uint2*)(hbuf + HB_PART + boff);
                    mma_tf32(dd, a[kt], (const uint32_t*)&uhi);
                    mma_tf32(dd, a[kt], (const uint32_t*)&ulo);
                }
                const int gc = warp * 16 + g;
                const int r0 = nt * 8 + 2 * tig;
                Dst[(size_t)r0 * GP + gc]           = dd[0];
                Dst[(size_t)(r0 + 1) * GP + gc]     = dd[1];
                Dst[(size_t)r0 * GP + gc + 8]       = dd[2];
                Dst[(size_t)(r0 + 1) * GP + gc + 8] = dd[3];
            }
            __syncthreads();
        }

        // gate update: 5 (row, hc) items per thread; c in registers
        float hval[5];
        int   urows[5], uhcs[5];
#pragma unroll
        for (int i = 0; i < 5; i++) {
            const int idx  = tid + 512 * i;
            const int urow = idx >> 6;
            const int uhc  = idx & 63;
            urows[i] = urow; uhcs[i] = uhc;
            const int gb = (uhc >> 2) * 16 + (uhc & 3) * 4;
            float4 dv = make_float4(0.f, 0.f, 0.f, 0.f);
            if (step > 0) dv = *(const float4*)&Dst[(size_t)urow * GP + gb];
            const float* xp = xgd + ((size_t)tin * NSEQ + row0 + urow) * G4
                            + jt * 64 + uhc;
            float pi = dv.x + xp[0];
            float pf = dv.y + xp[128];
            float pg = dv.z + xp[256];
            float po = dv.w + xp[384];
            float ig = sigm_(pi);
            float fg = sigm_(pf);
            float gg = tanh_(pg);
            float og = sigm_(po);
            float cn = fmaf(fg, c[i], ig * gg);
            c[i] = cn;
            hval[i] = og * tanh_(cn);
        }

        // publish h (hi/lo split) into local + partner hB buffers
        if (step < Lc - 1) {
            const int bufw = (step & 1) * HB_BUF;
#pragma unroll
            for (int i = 0; i < 5; i++) {
                const int k   = jt * 64 + uhcs[i];
                const int kt  = k >> 3;
                const int kp  = k & 3;
                const int hf  = (k >> 2) & 1;
                const int off = bufw + (kt * 4 + kp) * NP + urows[i] * 2 + hf;
                float hi = __uint_as_float(f2tf(hval[i]));
                float lo = __uint_as_float(f2tf(hval[i] - hi));
                hB[off]           = hi;
                hB[off + HB_PART] = lo;
                asm volatile("st.shared::cluster.f32 [%0], %1;"
                             :: "r"(hs_r + (uint32_t)off * 4u), "f"(hi)
                             : "memory");
                asm volatile("st.shared::cluster.f32 [%0], %1;"
                             :: "r"(hs_r + (uint32_t)(off + HB_PART) * 4u),
                                "f"(lo)
                             : "memory");
            }
            __syncthreads();   // local h visible + Dstage consumed block-wide
            asm volatile(
                "mbarrier.arrive.release.cluster.shared::cluster.b64 _, [%0];"
                :: "r"(mb_r) : "memory");
        }

        // layer output
#pragma unroll
        for (int i = 0; i < 5; i++)
            Xout[((size_t)(row0 + urows[i]) * Lc + tin) * 256
                 + dir * H + jt * 64 + uhcs[i]] = hval[i];
    }

    asm volatile("barrier.cluster.arrive.aligned;" ::: "memory");
    asm volatile("barrier.cluster.wait.aligned;" ::: "memory");
}

// ---------------------------------------------------------------------------
// Kernel 4: aggregation
// ---------------------------------------------------------------------------
__global__ __launch_bounds__(256) void agg_kernel(const float* __restrict__ X)
{
    int n = blockIdx.x, f = threadIdx.x;
    const float* base = X + (size_t)n * Lc * 256 + f;
    float s = 0.0f, m = -1e30f;
#pragma unroll 5
    for (int l = 0; l < Lc; l++) {
        float v = base[(size_t)l * 256];
        s += v; m = fmaxf(m, v);
    }
    g_agg[(size_t)n * 768 + f]       = s * (1.0f / Lc);
    g_agg[(size_t)n * 768 + 256 + f] = m;
    g_agg[(size_t)n * 768 + 512 + f] = (f < H) ? base[(Lc - 1) * 256] : base[0];
}

// ---------------------------------------------------------------------------
// Kernel 5: LayerNorm(512) + ReLU
// ---------------------------------------------------------------------------
__global__ __launch_bounds__(256) void ln_relu(
    const float* __restrict__ x, float* __restrict__ y,
    const float* __restrict__ gam, const float* __restrict__ bet)
{
    int row = blockIdx.x, tid = threadIdx.x;
    const float* xr = x + (size_t)row * 512;
    float v0 = xr[tid], v1 = xr[tid + 256];
    float s = v0 + v1, q = v0 * v0 + v1 * v1;
    __shared__ float ss[8], sq[8];
#pragma unroll
    for (int o = 16; o > 0; o >>= 1) {
        s += __shfl_down_sync(~0u, s, o);
        q += __shfl_down_sync(~0u, q, o);
    }
    int w = tid >> 5;
    if ((tid & 31) == 0) { ss[w] = s; sq[w] = q; }
    __syncthreads();
    if (tid == 0) {
        float S = 0.0f, Q = 0.0f;
        for (int i = 0; i < 8; i++) { S += ss[i]; Q += sq[i]; }
        ss[0] = S; sq[0] = Q;
    }
    __syncthreads();
    float mu  = ss[0] * (1.0f / 512.0f);
    float var = sq[0] * (1.0f / 512.0f) - mu * mu;
    float rs  = rsqrtf(var + 1e-5f);
    y[(size_t)row * 512 + tid]       = fmaxf((v0 - mu) * rs * gam[tid]       + bet[tid],       0.0f);
    y[(size_t)row * 512 + tid + 256] = fmaxf((v1 - mu) * rs * gam[tid + 256] + bet[tid + 256], 0.0f);
}

// ---------------------------------------------------------------------------
// Host orchestration
// ---------------------------------------------------------------------------
extern "C" void kernel_launch(void* const* d_in, const int* in_sizes, int n_in,
                              void* d_out, int out_size)
{
    const float* imu   = (const float*)d_in[0];
    const float* W_in  = (const float*)d_in[1];
    const float* b_in  = (const float*)d_in[2];
    const float* Wih[3] = {(const float*)d_in[3],  (const float*)d_in[7],  (const float*)d_in[11]};
    const float* Whh[3] = {(const float*)d_in[4],  (const float*)d_in[8],  (const float*)d_in[12]};
    const float* bih[3] = {(const float*)d_in[5],  (const float*)d_in[9],  (const float*)d_in[13]};
    const float* bhh[3] = {(const float*)d_in[6],  (const float*)d_in[10], (const float*)d_in[14]};
    const float* Wout1 = (const float*)d_in[15];
    const float* bout1 = (const float*)d_in[16];
    const float* ln_g  = (const float*)d_in[17];
    const float* ln_b  = (const float*)d_in[18];
    const float* Wout2 = (const float*)d_in[19];
    const float* bout2 = (const float*)d_in[20];
    float* out = (float*)d_out;

    float *pX0, *pXa, *pXb, *pxg, *pagg, *pt1, *pt2;
    cudaGetSymbolAddress((void**)&pX0,  g_X0);
    cudaGetSymbolAddress((void**)&pXa,  g_Xa);
    cudaGetSymbolAddress((void**)&pXb,  g_Xb);
    cudaGetSymbolAddress((void**)&pxg,  g_xg);
    cudaGetSymbolAddress((void**)&pagg, g_agg);
    cudaGetSymbolAddress((void**)&pt1,  g_t1);
    cudaGetSymbolAddress((void**)&pt2,  g_t2);

    cudaFuncSetAttribute(lstm_layer,
                         cudaFuncAttributeMaxDynamicSharedMemorySize, LSTM_SMEM);
    cudaFuncSetAttribute(tf32_gemm,
                         cudaFuncAttributeMaxDynamicSharedMemorySize, GEMM_SMEM);

    inproj_kernel<<<(NR * 64) / 256, 256>>>(imu, W_in, b_in);

    float* Xin  = pX0;
    int    Kin  = 64;
    float* Xout = pXa;
    for (int layer = 0; layer < 3; layer++) {
        // xg = Xin @ Wih + (bih+bhh); N=512 per dir -> nbx=2; both dirs in grid.x
        tf32_gemm<<<dim3(4, NR / 128), 256, GEMM_SMEM>>>(
            Xin, Wih[layer], pxg, bih[layer], bhh[layer],
            NR, G4, Kin,
            (long long)Kin * G4, (long long)NR * G4, (long long)G4, 2, 1);
        lstm_layer<<<128, 512, LSTM_SMEM>>>(Whh[layer], pxg, Xout);
        Xin = Xout;
        Kin = 256;
        Xout = (Xin == pXa) ? pXb : pXa;
    }
    float* Xfinal = Xin;

    agg_kernel<<<NSEQ, 256>>>(Xfinal);
    tf32_gemm<<<dim3(2, NSEQ / 128), 256, GEMM_SMEM>>>(
        pagg, Wout1, pt1, bout1, nullptr, NSEQ, 512, 768, 0, 0, 0, 2, 0);
    ln_relu<<<NSEQ, 256>>>(pt1, pt2, ln_g, ln_b);
    tf32_gemm<<<dim3(1, NSEQ / 128), 256, GEMM_SMEM>>>(
        pt2, Wout2, out, bout2, nullptr, NSEQ, 256, 512, 0, 0, 0, 1, 0);
}